// round 11
// baseline (speedup 1.0000x reference)
#include <cuda_runtime.h>
#include <cuda_bf16.h>
#include <math.h>
#include <stdint.h>

// ---------------- problem constants ----------------
#define NN   10000
#define DD   15
#define EE   320
#define OUTD 30
#define E2   (320*320)
#define LDP  644   // padded ld for 642-col mats

// ---------------- device scratch (no allocs allowed) ----------------
static __device__ float g_Fall[320*1920];
static __device__ float g_biasAll[1920];
static __device__ float g_Gq[E2];
static __device__ float g_Gkcat[640*320];
static __device__ float g_Gbig[641*320];
static __device__ float g_WoW[320*32];        // ld 32, 30 used
static __device__ float g_cq[320];
static __device__ float g_ckin[320];
static __device__ float g_ckout[320];
static __device__ float g_cvout[320];
static __device__ float g_Bpack[320*LDP];
static __device__ float g_Scoef[320*LDP];
static __device__ float g_GbW[641*32];        // ld 32, 30 used
static __device__ float g_bS[LDP];
static __device__ float g_b2[32];
static __device__ float g_XQKV[(size_t)NN*1920];
static __device__ float g_Og[(size_t)NN*32*320];
static __device__ float g_S2[(size_t)NN*LDP];

// ================= split-bf16 tensor-core GEMM (reg-prefetch pipelined) =================
// C = A(MxK,lda) @ B(KxN,ldb) + bias, fp32 in/out.
// Block tile 128x64, K-chunk 32. 8 warps: 4(M) x 2(N).
// Requires: K % 32 == 0, lda%4==0, ldb%4==0, ldc even, N even.
#define ASTR 40
#define BSTR 40

__device__ __forceinline__ void mma_bf16(float c[4], const uint32_t a[4], const uint32_t b[2])
{
    asm volatile(
        "mma.sync.aligned.m16n8k16.row.col.f32.bf16.bf16.f32 "
        "{%0,%1,%2,%3}, {%4,%5,%6,%7}, {%8,%9}, {%0,%1,%2,%3};\n"
        : "+f"(c[0]), "+f"(c[1]), "+f"(c[2]), "+f"(c[3])
        : "r"(a[0]), "r"(a[1]), "r"(a[2]), "r"(a[3]), "r"(b[0]), "r"(b[1]));
}

__global__ __launch_bounds__(256)
void gemm_tc(const float* __restrict__ A, int lda,
             const float* __restrict__ B, int ldb,
             const float* __restrict__ bias,
             float* __restrict__ C, int ldc,
             int M, int N, int K)
{
    __shared__ __nv_bfloat16 Ahi[128*ASTR];
    __shared__ __nv_bfloat16 Alo[128*ASTR];
    __shared__ __nv_bfloat16 Bhi[64*BSTR];
    __shared__ __nv_bfloat16 Blo[64*BSTR];

    const int tid  = threadIdx.x;
    const int lane = tid & 31, wid = tid >> 5;
    const int wm = (wid >> 1) * 32;
    const int wn = (wid & 1) * 32;
    const int bm = blockIdx.y * 128, bn = blockIdx.x * 64;

    float c[2][4][4];
    #pragma unroll
    for (int mt = 0; mt < 2; mt++)
        #pragma unroll
        for (int nt = 0; nt < 4; nt++)
            #pragma unroll
            for (int r = 0; r < 4; r++) c[mt][nt][r] = 0.f;

    const int lq = lane >> 2;
    const int lr2 = (lane & 3) * 2;

    const int a_row = tid >> 3, a_k4 = (tid & 7) * 4;
    const int b_kk  = tid >> 4, b_n4 = (tid & 15) * 4;

    float4 ra[4];
    float  rb[2][4];

    auto load_regs = [&](int k0) {
        #pragma unroll
        for (int i = 0; i < 4; i++) {
            int gm = bm + a_row + i*32;
            ra[i] = (gm < M) ? *(const float4*)(A + (size_t)gm*lda + k0 + a_k4)
                             : make_float4(0.f,0.f,0.f,0.f);
        }
        #pragma unroll
        for (int i = 0; i < 2; i++) {
            const float* bp = B + (size_t)(k0 + b_kk + i*16)*ldb + bn + b_n4;
            #pragma unroll
            for (int j = 0; j < 4; j++)
                rb[i][j] = (bn + b_n4 + j < N) ? bp[j] : 0.f;
        }
    };
    auto store_smem = [&]() {
        #pragma unroll
        for (int i = 0; i < 4; i++) {
            int row = a_row + i*32;
            float vv[4] = {ra[i].x, ra[i].y, ra[i].z, ra[i].w};
            #pragma unroll
            for (int j = 0; j < 4; j += 2) {
                __nv_bfloat16 h0 = __float2bfloat16(vv[j]);
                __nv_bfloat16 h1 = __float2bfloat16(vv[j+1]);
                __nv_bfloat16 l0 = __float2bfloat16(vv[j]   - __bfloat162float(h0));
                __nv_bfloat16 l1 = __float2bfloat16(vv[j+1] - __bfloat162float(h1));
                *(__nv_bfloat162*)&Ahi[row*ASTR + a_k4 + j] = __nv_bfloat162(h0, h1);
                *(__nv_bfloat162*)&Alo[row*ASTR + a_k4 + j] = __nv_bfloat162(l0, l1);
            }
        }
        #pragma unroll
        for (int i = 0; i < 2; i++) {
            int kk = b_kk + i*16;
            #pragma unroll
            for (int j = 0; j < 4; j++) {
                float x = rb[i][j];
                __nv_bfloat16 h = __float2bfloat16(x);
                __nv_bfloat16 l = __float2bfloat16(x - __bfloat162float(h));
                Bhi[(b_n4 + j)*BSTR + kk] = h;
                Blo[(b_n4 + j)*BSTR + kk] = l;
            }
        }
    };

    load_regs(0);
    store_smem();
    __syncthreads();

    for (int k0 = 0; k0 < K; k0 += 32) {
        const bool has_next = (k0 + 32 < K);
        if (has_next) load_regs(k0 + 32);

        #pragma unroll
        for (int kk = 0; kk < 32; kk += 16) {
            uint32_t bh[4][2], bl[4][2];
            #pragma unroll
            for (int nt = 0; nt < 4; nt++) {
                int n = wn + nt*8 + lq;
                int kb = kk + lr2;
                bh[nt][0] = *(const uint32_t*)&Bhi[n*BSTR + kb];
                bh[nt][1] = *(const uint32_t*)&Bhi[n*BSTR + kb + 8];
                bl[nt][0] = *(const uint32_t*)&Blo[n*BSTR + kb];
                bl[nt][1] = *(const uint32_t*)&Blo[n*BSTR + kb + 8];
            }
            #pragma unroll
            for (int mt = 0; mt < 2; mt++) {
                int r = wm + mt*16 + lq;
                int ka = kk + lr2;
                uint32_t ah[4], al[4];
                ah[0] = *(const uint32_t*)&Ahi[r*ASTR + ka];
                ah[1] = *(const uint32_t*)&Ahi[(r+8)*ASTR + ka];
                ah[2] = *(const uint32_t*)&Ahi[r*ASTR + ka + 8];
                ah[3] = *(const uint32_t*)&Ahi[(r+8)*ASTR + ka + 8];
                al[0] = *(const uint32_t*)&Alo[r*ASTR + ka];
                al[1] = *(const uint32_t*)&Alo[(r+8)*ASTR + ka];
                al[2] = *(const uint32_t*)&Alo[r*ASTR + ka + 8];
                al[3] = *(const uint32_t*)&Alo[(r+8)*ASTR + ka + 8];
                #pragma unroll
                for (int nt = 0; nt < 4; nt++) {
                    mma_bf16(c[mt][nt], ah, bh[nt]);
                    mma_bf16(c[mt][nt], ah, bl[nt]);
                    mma_bf16(c[mt][nt], al, bh[nt]);
                }
            }
        }
        if (has_next) {
            __syncthreads();
            store_smem();
            __syncthreads();
        }
    }

    #pragma unroll
    for (int mt = 0; mt < 2; mt++) {
        #pragma unroll
        for (int nt = 0; nt < 4; nt++) {
            int col = bn + wn + nt*8 + lr2;
            if (col >= N) continue;
            float b0 = bias ? bias[col]   : 0.f;
            float b1 = bias ? bias[col+1] : 0.f;
            int row0 = bm + wm + mt*16 + lq;
            int row1 = row0 + 8;
            if (row0 < M)
                *(float2*)(C + (size_t)row0*ldc + col) =
                    make_float2(c[mt][nt][0] + b0, c[mt][nt][1] + b1);
            if (row1 < M)
                *(float2*)(C + (size_t)row1*ldc + col) =
                    make_float2(c[mt][nt][2] + b0, c[mt][nt][3] + b1);
        }
    }
}

// ---------------- batched weight-prep GEMM (64x64 tile, runtime tra/trb) ----------------
struct WDesc {
    const float* A; const float* B; float* C;
    int lda, ldb, ldc, M, N, K, tra, trb;
};
struct WDescArr { WDesc d[13]; };

__global__ __launch_bounds__(256)
void gemm_w_batched(WDescArr descs)
{
    const WDesc w = descs.d[blockIdx.z];
    __shared__ float As[16][68];
    __shared__ float Bs[16][68];
    const int tid = threadIdx.x;
    const int tx = tid & 15, ty = tid >> 4;
    const int bm = blockIdx.y * 64, bn = blockIdx.x * 64;
    if (bm >= w.M || bn >= w.N) return;
    float acc[4][4] = {};

    for (int k0 = 0; k0 < w.K; k0 += 16) {
        if (!w.tra) {
            int kk = tid & 15, m0 = tid >> 4;
            #pragma unroll
            for (int i = 0; i < 4; i++) {
                int mm = m0 + i*16;
                int gm = bm + mm, gk = k0 + kk;
                As[kk][mm] = (gm < w.M && gk < w.K) ? w.A[(size_t)gm*w.lda + gk] : 0.f;
            }
        } else {
            int mm = tid & 63, kq = tid >> 6;
            #pragma unroll
            for (int i = 0; i < 4; i++) {
                int kk = kq + i*4;
                int gm = bm + mm, gk = k0 + kk;
                As[kk][mm] = (gm < w.M && gk < w.K) ? w.A[(size_t)gk*w.lda + gm] : 0.f;
            }
        }
        if (!w.trb) {
            int nn = tid & 63, kq = tid >> 6;
            #pragma unroll
            for (int i = 0; i < 4; i++) {
                int kk = kq + i*4;
                int gk = k0 + kk, gn = bn + nn;
                Bs[kk][nn] = (gk < w.K && gn < w.N) ? w.B[(size_t)gk*w.ldb + gn] : 0.f;
            }
        } else {
            int kk = tid & 15, n0 = tid >> 4;
            #pragma unroll
            for (int i = 0; i < 4; i++) {
                int nn = n0 + i*16;
                int gk = k0 + kk, gn = bn + nn;
                Bs[kk][nn] = (gk < w.K && gn < w.N) ? w.B[(size_t)gn*w.ldb + gk] : 0.f;
            }
        }
        __syncthreads();
        #pragma unroll
        for (int kk = 0; kk < 16; kk++) {
            float4 a = *(const float4*)&As[kk][ty*4];
            float4 b = *(const float4*)&Bs[kk][tx*4];
            acc[0][0] += a.x*b.x; acc[0][1] += a.x*b.y; acc[0][2] += a.x*b.z; acc[0][3] += a.x*b.w;
            acc[1][0] += a.y*b.x; acc[1][1] += a.y*b.y; acc[1][2] += a.y*b.z; acc[1][3] += a.y*b.w;
            acc[2][0] += a.z*b.x; acc[2][1] += a.z*b.y; acc[2][2] += a.z*b.z; acc[2][3] += a.z*b.w;
            acc[3][0] += a.w*b.x; acc[3][1] += a.w*b.y; acc[3][2] += a.w*b.z; acc[3][3] += a.w*b.w;
        }
        __syncthreads();
    }
    #pragma unroll
    for (int i = 0; i < 4; i++) {
        int gm = bm + ty*4 + i;
        if (gm >= w.M) continue;
        #pragma unroll
        for (int j = 0; j < 4; j++) {
            int gn = bn + tx*4 + j;
            if (gn >= w.N) continue;
            w.C[(size_t)gm*w.ldc + gn] = acc[i][j];
        }
    }
}

// ---------------- small vector prep ----------------
__global__ void prep_vectors(const float* __restrict__ in_qkv_b, const float* __restrict__ out_qkv_b,
                             const float* __restrict__ in_o_b, const float* __restrict__ out_o_b,
                             const float* __restrict__ fin_qkv_w, const float* __restrict__ fin_qkv_b)
{
    int b = blockIdx.x, t = threadIdx.x; // 320 threads
    if (b < 6) {
        int i = b*320 + t;
        g_biasAll[i] = (i < 960) ? in_qkv_b[i] : out_qkv_b[i - 960];
    } else if (b == 6) {
        float s = fin_qkv_b[t];
        const float* w = fin_qkv_w;
        for (int k = 0; k < 320; k++) s += in_o_b[k] * w[t*320 + k];
        g_cq[t] = s;
    } else if (b == 7) {
        float s = fin_qkv_b[320 + t];
        const float* w = fin_qkv_w + E2;
        for (int k = 0; k < 320; k++) s += in_o_b[k] * w[t*320 + k];
        g_ckin[t] = s;
    } else if (b == 8) {
        float s = fin_qkv_b[320 + t];
        const float* w = fin_qkv_w + E2;
        for (int k = 0; k < 320; k++) s += out_o_b[k] * w[t*320 + k];
        g_ckout[t] = s;
    } else if (b == 9) {
        float s = fin_qkv_b[640 + t];
        const float* w = fin_qkv_w + 2*E2;
        for (int k = 0; k < 320; k++) s += out_o_b[k] * w[t*320 + k];
        g_cvout[t] = s;
    } else if (b == 10) {
        float s = 0.f;
        const float* w = fin_qkv_w + 2*E2;
        for (int k = 0; k < 320; k++) s += (in_o_b[k] - out_o_b[k]) * w[t*320 + k];
        g_Gbig[640*320 + t] = s;
    }
}

// Bpack[k][j] = Gkcat[j][k] (j<640) ; ckin (640) ; ckout (641); pad 0
__global__ void pack_B_kernel()
{
    int k = blockIdx.x;
    int j = threadIdx.x;
    float v;
    if (j < 640)       v = g_Gkcat[(size_t)j*320 + k];
    else if (j == 640) v = g_ckin[k];
    else if (j == 641) v = g_ckout[k];
    else               v = 0.f;
    g_Bpack[(size_t)k*LDP + j] = v;
}

// bias vectors: blocks 0..641 -> bS dot; 642..643 -> bS pad zero; 644..673 -> b2
__global__ void bias_kernel(const float* __restrict__ fin_o_b, const float* __restrict__ Wm)
{
    __shared__ float red[4];
    int b = blockIdx.x, t = threadIdx.x; // 128 threads
    if (b >= 642 && b < 644) { if (t == 0) g_bS[b] = 0.f; return; }
    float p = 0.f;
    if (b < 642) {
        for (int k = t; k < 320; k += 128) p += g_cq[k] * g_Bpack[(size_t)k*LDP + b];
    } else {
        int j = b - 644; // < 30
        for (int k = t; k < 320; k += 128)
            p += g_cvout[k] * g_WoW[k*32 + j] + fin_o_b[k] * Wm[k*OUTD + j];
    }
    #pragma unroll
    for (int o = 16; o; o >>= 1) p += __shfl_down_sync(0xffffffffu, p, o);
    if ((t & 31) == 0) red[t >> 5] = p;
    __syncthreads();
    if (t == 0) {
        float s = red[0] + red[1] + red[2] + red[3];
        if (b < 642) g_bS[b] = s; else g_b2[b - 644] = s;
    }
}

// ---------------- per-node in/out attention (256 threads) ----------------
__global__ __launch_bounds__(256)
void attn_inout_kernel(const float* __restrict__ XQKV,
                       const int* __restrict__ in_idx,
                       const int* __restrict__ out_idx,
                       float* __restrict__ Og)
{
    extern __shared__ float sm[];
    float* Qs = sm;                 // 16*324
    float* Ks = Qs + 16*324;
    float* Vs = Ks + 16*324;
    float* Asc = Vs + 16*324;       // 5*256
    int* tok = (int*)(Asc + 5*256);

    const int node = blockIdx.x;
    const int layer = blockIdx.y;
    const int tid = threadIdx.x;
    const int* idx = layer ? out_idx : in_idx;
    const int qoff = layer * 960;

    if (tid < 16) tok[tid] = (tid == 0) ? node : idx[node*DD + tid - 1];
    __syncthreads();

    for (int t = tid; t < 3*16*80; t += 256) {
        int mat = t / 1280;
        int rem = t - mat*1280;
        int r = rem / 80;
        int e4 = rem - r*80;
        float4 v = *(const float4*)(XQKV + (size_t)tok[r]*1920 + qoff + mat*320 + e4*4);
        *(float4*)(sm + mat*(16*324) + r*324 + e4*4) = v;
    }
    __syncthreads();

    // scores: 160 threads, 2x4 tiles per thread (h, l-pair, m-quad)
    if (tid < 160) {
        int h  = tid >> 5;          // 0..4
        int r  = tid & 31;
        int lb = r >> 2;            // 0..7  (pair of l rows)
        int mb = r & 3;             // 0..3  (quad of m cols)
        float s[2][4] = {};
        const float* qb = Qs + lb*2*324 + h*64;
        const float* kb = Ks + mb*4*324 + h*64;
        #pragma unroll
        for (int k4 = 0; k4 < 16; k4++) {
            float4 qv[2], kv[4];
            #pragma unroll
            for (int i = 0; i < 2; i++) qv[i] = *(const float4*)(qb + i*324 + k4*4);
            #pragma unroll
            for (int j = 0; j < 4; j++) kv[j] = *(const float4*)(kb + j*324 + k4*4);
            #pragma unroll
            for (int i = 0; i < 2; i++)
                #pragma unroll
                for (int j = 0; j < 4; j++)
                    s[i][j] += qv[i].x*kv[j].x + qv[i].y*kv[j].y + qv[i].z*kv[j].z + qv[i].w*kv[j].w;
        }
        #pragma unroll
        for (int i = 0; i < 2; i++)
            #pragma unroll
            for (int j = 0; j < 4; j++)
                Asc[h*256 + (lb*2+i)*16 + (mb*4+j)] = s[i][j] * 0.125f;
    }
    __syncthreads();

    if (tid < 80) {
        int h = tid / 16, l = tid & 15;
        float* row = Asc + h*256 + l*16;
        float mx = row[0];
        #pragma unroll
        for (int m = 1; m < 16; m++) mx = fmaxf(mx, row[m]);
        float e[16]; float ssum = 0.f;
        #pragma unroll
        for (int m = 0; m < 16; m++) { e[m] = __expf(row[m] - mx); ssum += e[m]; }
        float inv = 1.f / ssum;
        #pragma unroll
        for (int m = 0; m < 16; m++) row[m] = e[m] * inv;
    }
    __syncthreads();

    float* Ob = Og + ((size_t)node*32 + layer*16)*320;
    if (tid < 160) {
        int lb = tid / 40, e8 = tid - lb*40;
        int h = e8 >> 3;
        float acc[4][8] = {};
        #pragma unroll
        for (int m = 0; m < 16; m++) {
            const float* vp = Vs + m*324 + e8*8;
            float4 v0 = *(const float4*)vp;
            float4 v1 = *(const float4*)(vp + 4);
            #pragma unroll
            for (int i = 0; i < 4; i++) {
                float a = Asc[h*256 + (lb*4+i)*16 + m];
                acc[i][0] += a*v0.x; acc[i][1] += a*v0.y; acc[i][2] += a*v0.z; acc[i][3] += a*v0.w;
                acc[i][4] += a*v1.x; acc[i][5] += a*v1.y; acc[i][6] += a*v1.z; acc[i][7] += a*v1.w;
            }
        }
        #pragma unroll
        for (int i = 0; i < 4; i++) {
            float* op = Ob + (lb*4+i)*320 + e8*8;
            *(float4*)op       = make_float4(acc[i][0], acc[i][1], acc[i][2], acc[i][3]);
            *(float4*)(op + 4) = make_float4(acc[i][4], acc[i][5], acc[i][6], acc[i][7]);
        }
    }
}

// ---------------- per-node final attention + fused output projection (256 thr) ----------------
__global__ __launch_bounds__(256)
void fin_kernel(const float* __restrict__ Og, const float* __restrict__ S2,
                float* __restrict__ out)
{
    extern __shared__ float sm[];
    float* Os  = sm;             // 32*324
    float* Ss  = Os + 32*324;    // 644
    float* red = Ss + 644;       // 256
    float* aw  = red + 256;      // [0..31]=a, [32]=a_in_tot

    const int node = blockIdx.x;
    const int tid = threadIdx.x;

    for (int t = tid; t < 642; t += 256) Ss[t] = S2[(size_t)node*LDP + t];
    for (int t = tid; t < 32*80; t += 256) {
        int r = t / 80, e4 = t - r*80;
        *(float4*)(Os + r*324 + e4*4) = *(const float4*)(Og + ((size_t)node*32 + r)*320 + e4*4);
    }
    __syncthreads();

    {
        int m = tid >> 3, s8 = tid & 7;
        const float* Sx = Ss + ((m < 16) ? 0 : 320);
        const float* Om = Os + m*324;
        float p = 0.f;
        #pragma unroll
        for (int e = s8*40; e < s8*40 + 40; e++) p += Sx[e] * Om[e];
        red[tid] = p;
    }
    __syncthreads();

    if (tid < 32) {
        float sc = 0.f;
        #pragma unroll
        for (int s = 0; s < 8; s++) sc += red[tid*8 + s];
        sc += (tid < 16) ? Ss[640] : Ss[641];
        sc *= 0.0559016994f;  // 1/sqrt(320)
        float mx = sc;
        #pragma unroll
        for (int o = 16; o; o >>= 1) mx = fmaxf(mx, __shfl_xor_sync(0xffffffffu, mx, o));
        float ex = __expf(sc - mx);
        float ssum = ex;
        #pragma unroll
        for (int o = 16; o; o >>= 1) ssum += __shfl_xor_sync(0xffffffffu, ssum, o);
        float a = ex / ssum;
        aw[tid] = a;
        float ain = (tid < 16) ? a : 0.f;
        #pragma unroll
        for (int o = 16; o; o >>= 1) ain += __shfl_xor_sync(0xffffffffu, ain, o);
        if (tid == 0) aw[32] = ain;
    }
    __syncthreads();

    for (int t = tid; t < 640; t += 256) {
        int which = t / 320, e = t - which*320;
        float acc = 0.f;
        #pragma unroll
        for (int m = 0; m < 16; m++) acc += aw[which*16 + m] * Os[(which*16 + m)*324 + e];
        Ss[t] = acc;
    }
    if (tid == 0) Ss[640] = aw[32];
    __syncthreads();

    if (tid < 240) {
        int j = tid >> 3, s = tid & 7;
        float p = 0.f;
        for (int k = s; k < 641; k += 8) p += Ss[k] * g_GbW[k*32 + j];
        red[tid] = p;
    }
    __syncthreads();
    if (tid < 30) {
        float v = g_b2[tid];
        #pragma unroll
        for (int s = 0; s < 8; s++) v += red[tid*8 + s];
        v = (v > 0.f) ? v : (__expf(v) - 1.f);
        out[(size_t)node*OUTD + tid] = v;
    }
}

// ---------------- host launcher ----------------
extern "C" void kernel_launch(void* const* d_in, const int* in_sizes, int n_in,
                              void* d_out, int out_size)
{
    const float* X        = (const float*)d_in[0];
    const int*   in_idx   = (const int*)  d_in[1];
    const int*   out_idx  = (const int*)  d_in[2];
    const float* in_Wq    = (const float*)d_in[3];
    const float* in_Wk    = (const float*)d_in[4];
    const float* in_Wv    = (const float*)d_in[5];
    const float* in_qkv_w = (const float*)d_in[6];
    const float* in_qkv_b = (const float*)d_in[7];
    const float* in_o_w   = (const float*)d_in[8];
    const float* in_o_b   = (const float*)d_in[9];
    const float* out_Wq   = (const float*)d_in[10];
    const float* out_Wk   = (const float*)d_in[11];
    const float* out_Wv   = (const float*)d_in[12];
    const float* out_qkv_w= (const float*)d_in[13];
    const float* out_qkv_b= (const float*)d_in[14];
    const float* out_o_w  = (const float*)d_in[15];
    const float* out_o_b  = (const float*)d_in[16];
    const float* fin_qkv_w= (const float*)d_in[17];
    const float* fin_qkv_b= (const float*)d_in[18];
    const float* fin_o_w  = (const float*)d_in[19];
    const float* fin_o_b  = (const float*)d_in[20];
    const float* Wm       = (const float*)d_in[21];
    float* out = (float*)d_out;

    float *Fall, *biasAll, *Gq, *Gkcat, *Gbig, *WoW;
    float *Bpack, *Scoef, *GbW, *bS;
    float *XQKV, *Og, *S2;
    cudaGetSymbolAddress((void**)&Fall,   g_Fall);
    cudaGetSymbolAddress((void**)&biasAll,g_biasAll);
    cudaGetSymbolAddress((void**)&Gq,     g_Gq);
    cudaGetSymbolAddress((void**)&Gkcat,  g_Gkcat);
    cudaGetSymbolAddress((void**)&Gbig,   g_Gbig);
    cudaGetSymbolAddress((void**)&WoW,    g_WoW);
    cudaGetSymbolAddress((void**)&Bpack,  g_Bpack);
    cudaGetSymbolAddress((void**)&Scoef,  g_Scoef);
    cudaGetSymbolAddress((void**)&GbW,    g_GbW);
    cudaGetSymbolAddress((void**)&bS,     g_bS);
    cudaGetSymbolAddress((void**)&XQKV,   g_XQKV);
    cudaGetSymbolAddress((void**)&Og,     g_Og);
    cudaGetSymbolAddress((void**)&S2,     g_S2);

    const int attn_smem = (3*16*324 + 5*256)*4 + 16*4;
    const int fin_smem  = (32*324 + 644 + 256 + 40)*4;
    cudaFuncSetAttribute(attn_inout_kernel, cudaFuncAttributeMaxDynamicSharedMemorySize, attn_smem);
    cudaFuncSetAttribute(fin_kernel,        cudaFuncAttributeMaxDynamicSharedMemorySize, fin_smem);

    // 1) small vector prep
    prep_vectors<<<11, 320>>>(in_qkv_b, out_qkv_b, in_o_b, out_o_b, fin_qkv_w, fin_qkv_b);

    // 2) batched weight-prep GEMMs
    WDescArr wd;
    const float* Wc[6]  = {in_Wq, in_Wk, in_Wv, out_Wq, out_Wk, out_Wv};
    const float* Wp[6]  = {in_qkv_w, in_qkv_w + E2, in_qkv_w + 2*E2,
                           out_qkv_w, out_qkv_w + E2, out_qkv_w + 2*E2};
    for (int i = 0; i < 6; i++)
        wd.d[i] = WDesc{Wc[i], Wp[i], Fall + i*320, 320, 320, 1920, 320, 320, 320, 0, 1};
    wd.d[6]  = WDesc{in_o_w,  fin_qkv_w,        Gq,        320, 320, 320, 320, 320, 320, 1, 1};
    wd.d[7]  = WDesc{in_o_w,  fin_qkv_w + E2,   Gkcat,     320, 320, 320, 320, 320, 320, 1, 1};
    wd.d[8]  = WDesc{out_o_w, fin_qkv_w + E2,   Gkcat+E2,  320, 320, 320, 320, 320, 320, 1, 1};
    wd.d[9]  = WDesc{in_o_w,  fin_qkv_w + 2*E2, Gbig,      320, 320, 320, 320, 320, 320, 1, 1};
    wd.d[10] = WDesc{out_o_w, fin_qkv_w + 2*E2, Gbig+E2,   320, 320, 320, 320, 320, 320, 1, 1};
    wd.d[11] = WDesc{fin_o_w, Wm, WoW, 320, OUTD, 32, 320, OUTD, 320, 1, 0};
    wd.d[12] = wd.d[11]; // unused
    gemm_w_batched<<<dim3(5, 5, 12), 256>>>(wd);

    // 3) pack B (ld 644)
    pack_B_kernel<<<320, LDP>>>();

    // 4) Scoef = Gq @ Bpack   [320,642] — tensor cores (pipelined)
    gemm_tc<<<dim3(11, 3), 256>>>(Gq, 320, Bpack, LDP, nullptr, Scoef, LDP, 320, 642, 320);
    // 5) GbW = Gbig @ WoW     [641,30]
    {
        WDescArr w2;
        for (int i = 0; i < 13; i++)
            w2.d[i] = WDesc{Gbig, WoW, GbW, 320, 32, 32, 641, OUTD, 320, 0, 0};
        gemm_w_batched<<<dim3(1, 11, 1), 256>>>(w2);
    }
    // 6) bias vectors (includes bS pad zeroing)
    bias_kernel<<<674, 128>>>(fin_o_b, Wm);

    // 7) XQKV = X @ Fall + biasAll   [10000,1920]  — tensor cores
    gemm_tc<<<dim3(30, 79), 256>>>(X, 320, Fall, 1920, biasAll, XQKV, 1920, NN, 1920, 320);

    // 8) per-node in/out attention -> Og [N,32,320]
    attn_inout_kernel<<<dim3(NN, 2), 256, attn_smem>>>(XQKV, in_idx, out_idx, Og);

    // 9) S2 = O0_in @ Scoef + bS   [10000,642] — tensor cores
    gemm_tc<<<dim3(11, 79), 256>>>(Og, 32*320, Scoef, LDP, bS, S2, LDP, NN, 642, 320);

    // 10) per-node final softmax + weighted sums + fused out projection
    fin_kernel<<<NN, 256, fin_smem>>>(Og, S2, out);
}

// round 12
// speedup vs baseline: 1.0447x; 1.0447x over previous
#include <cuda_runtime.h>
#include <cuda_bf16.h>
#include <math.h>
#include <stdint.h>

// ---------------- problem constants ----------------
#define NN   10000
#define DD   15
#define EE   320
#define OUTD 30
#define E2   (320*320)
#define LDP  644   // padded ld for 642-col mats

// ---------------- device scratch (no allocs allowed) ----------------
static __device__ float g_Fall[320*1920];
static __device__ float g_biasAll[1920];
static __device__ float g_Gq[E2];
static __device__ float g_Gkcat[640*320];
static __device__ float g_Gbig[641*320];
static __device__ float g_WoW[320*32];        // ld 32, 30 used
static __device__ float g_cq[320];
static __device__ float g_ckin[320];
static __device__ float g_ckout[320];
static __device__ float g_cvout[320];
static __device__ float g_Bpack[320*LDP];
static __device__ float g_Scoef[320*LDP];
static __device__ float g_GbW[641*32];        // ld 32, 30 used
static __device__ float g_bS[LDP];
static __device__ float g_b2[32];
static __device__ float g_XQKV[(size_t)NN*1920];
static __device__ float g_Og[(size_t)NN*32*320];
static __device__ float g_S2[(size_t)NN*LDP];

// ================= split-bf16 tensor-core GEMM (reg-prefetch pipelined) =================
// C = A(MxK,lda) @ B(KxN,ldb) + bias, fp32 in/out.
// Block tile 128x64, K-chunk 32. 8 warps: 4(M) x 2(N).
// Requires: K % 32 == 0, lda%4==0, ldb%4==0, ldc even, N even.
#define ASTR 40
#define BSTR 40

__device__ __forceinline__ void mma_bf16(float c[4], const uint32_t a[4], const uint32_t b[2])
{
    asm volatile(
        "mma.sync.aligned.m16n8k16.row.col.f32.bf16.bf16.f32 "
        "{%0,%1,%2,%3}, {%4,%5,%6,%7}, {%8,%9}, {%0,%1,%2,%3};\n"
        : "+f"(c[0]), "+f"(c[1]), "+f"(c[2]), "+f"(c[3])
        : "r"(a[0]), "r"(a[1]), "r"(a[2]), "r"(a[3]), "r"(b[0]), "r"(b[1]));
}

__global__ __launch_bounds__(256)
void gemm_tc(const float* __restrict__ A, int lda,
             const float* __restrict__ B, int ldb,
             const float* __restrict__ bias,
             float* __restrict__ C, int ldc,
             int M, int N, int K)
{
    __shared__ __nv_bfloat16 Ahi[128*ASTR];
    __shared__ __nv_bfloat16 Alo[128*ASTR];
    __shared__ __nv_bfloat16 Bhi[64*BSTR];
    __shared__ __nv_bfloat16 Blo[64*BSTR];

    const int tid  = threadIdx.x;
    const int lane = tid & 31, wid = tid >> 5;
    const int wm = (wid >> 1) * 32;
    const int wn = (wid & 1) * 32;
    const int bm = blockIdx.y * 128, bn = blockIdx.x * 64;

    float c[2][4][4];
    #pragma unroll
    for (int mt = 0; mt < 2; mt++)
        #pragma unroll
        for (int nt = 0; nt < 4; nt++)
            #pragma unroll
            for (int r = 0; r < 4; r++) c[mt][nt][r] = 0.f;

    const int lq = lane >> 2;
    const int lr2 = (lane & 3) * 2;

    const int a_row = tid >> 3, a_k4 = (tid & 7) * 4;
    const int b_kk  = tid >> 4, b_n4 = (tid & 15) * 4;

    float4 ra[4];
    float  rb[2][4];

    auto load_regs = [&](int k0) {
        #pragma unroll
        for (int i = 0; i < 4; i++) {
            int gm = bm + a_row + i*32;
            ra[i] = (gm < M) ? *(const float4*)(A + (size_t)gm*lda + k0 + a_k4)
                             : make_float4(0.f,0.f,0.f,0.f);
        }
        #pragma unroll
        for (int i = 0; i < 2; i++) {
            const float* bp = B + (size_t)(k0 + b_kk + i*16)*ldb + bn + b_n4;
            #pragma unroll
            for (int j = 0; j < 4; j++)
                rb[i][j] = (bn + b_n4 + j < N) ? bp[j] : 0.f;
        }
    };
    auto store_smem = [&]() {
        #pragma unroll
        for (int i = 0; i < 4; i++) {
            int row = a_row + i*32;
            float vv[4] = {ra[i].x, ra[i].y, ra[i].z, ra[i].w};
            #pragma unroll
            for (int j = 0; j < 4; j += 2) {
                __nv_bfloat16 h0 = __float2bfloat16(vv[j]);
                __nv_bfloat16 h1 = __float2bfloat16(vv[j+1]);
                __nv_bfloat16 l0 = __float2bfloat16(vv[j]   - __bfloat162float(h0));
                __nv_bfloat16 l1 = __float2bfloat16(vv[j+1] - __bfloat162float(h1));
                *(__nv_bfloat162*)&Ahi[row*ASTR + a_k4 + j] = __nv_bfloat162(h0, h1);
                *(__nv_bfloat162*)&Alo[row*ASTR + a_k4 + j] = __nv_bfloat162(l0, l1);
            }
        }
        #pragma unroll
        for (int i = 0; i < 2; i++) {
            int kk = b_kk + i*16;
            #pragma unroll
            for (int j = 0; j < 4; j++) {
                float x = rb[i][j];
                __nv_bfloat16 h = __float2bfloat16(x);
                __nv_bfloat16 l = __float2bfloat16(x - __bfloat162float(h));
                Bhi[(b_n4 + j)*BSTR + kk] = h;
                Blo[(b_n4 + j)*BSTR + kk] = l;
            }
        }
    };

    load_regs(0);
    store_smem();
    __syncthreads();

    for (int k0 = 0; k0 < K; k0 += 32) {
        const bool has_next = (k0 + 32 < K);
        if (has_next) load_regs(k0 + 32);

        #pragma unroll
        for (int kk = 0; kk < 32; kk += 16) {
            uint32_t bh[4][2], bl[4][2];
            #pragma unroll
            for (int nt = 0; nt < 4; nt++) {
                int n = wn + nt*8 + lq;
                int kb = kk + lr2;
                bh[nt][0] = *(const uint32_t*)&Bhi[n*BSTR + kb];
                bh[nt][1] = *(const uint32_t*)&Bhi[n*BSTR + kb + 8];
                bl[nt][0] = *(const uint32_t*)&Blo[n*BSTR + kb];
                bl[nt][1] = *(const uint32_t*)&Blo[n*BSTR + kb + 8];
            }
            #pragma unroll
            for (int mt = 0; mt < 2; mt++) {
                int r = wm + mt*16 + lq;
                int ka = kk + lr2;
                uint32_t ah[4], al[4];
                ah[0] = *(const uint32_t*)&Ahi[r*ASTR + ka];
                ah[1] = *(const uint32_t*)&Ahi[(r+8)*ASTR + ka];
                ah[2] = *(const uint32_t*)&Ahi[r*ASTR + ka + 8];
                ah[3] = *(const uint32_t*)&Ahi[(r+8)*ASTR + ka + 8];
                al[0] = *(const uint32_t*)&Alo[r*ASTR + ka];
                al[1] = *(const uint32_t*)&Alo[(r+8)*ASTR + ka];
                al[2] = *(const uint32_t*)&Alo[r*ASTR + ka + 8];
                al[3] = *(const uint32_t*)&Alo[(r+8)*ASTR + ka + 8];
                #pragma unroll
                for (int nt = 0; nt < 4; nt++) {
                    mma_bf16(c[mt][nt], ah, bh[nt]);
                    mma_bf16(c[mt][nt], ah, bl[nt]);
                    mma_bf16(c[mt][nt], al, bh[nt]);
                }
            }
        }
        if (has_next) {
            __syncthreads();
            store_smem();
            __syncthreads();
        }
    }

    #pragma unroll
    for (int mt = 0; mt < 2; mt++) {
        #pragma unroll
        for (int nt = 0; nt < 4; nt++) {
            int col = bn + wn + nt*8 + lr2;
            if (col >= N) continue;
            float b0 = bias ? bias[col]   : 0.f;
            float b1 = bias ? bias[col+1] : 0.f;
            int row0 = bm + wm + mt*16 + lq;
            int row1 = row0 + 8;
            if (row0 < M)
                *(float2*)(C + (size_t)row0*ldc + col) =
                    make_float2(c[mt][nt][0] + b0, c[mt][nt][1] + b1);
            if (row1 < M)
                *(float2*)(C + (size_t)row1*ldc + col) =
                    make_float2(c[mt][nt][2] + b0, c[mt][nt][3] + b1);
        }
    }
}

// ---------------- batched weight-prep GEMM (64x64 tile, runtime tra/trb) ----------------
struct WDesc {
    const float* A; const float* B; float* C;
    int lda, ldb, ldc, M, N, K, tra, trb;
};
struct WDescArr { WDesc d[13]; };

__global__ __launch_bounds__(256)
void gemm_w_batched(WDescArr descs)
{
    const WDesc w = descs.d[blockIdx.z];
    __shared__ float As[16][68];
    __shared__ float Bs[16][68];
    const int tid = threadIdx.x;
    const int tx = tid & 15, ty = tid >> 4;
    const int bm = blockIdx.y * 64, bn = blockIdx.x * 64;
    if (bm >= w.M || bn >= w.N) return;
    float acc[4][4] = {};

    for (int k0 = 0; k0 < w.K; k0 += 16) {
        if (!w.tra) {
            int kk = tid & 15, m0 = tid >> 4;
            #pragma unroll
            for (int i = 0; i < 4; i++) {
                int mm = m0 + i*16;
                int gm = bm + mm, gk = k0 + kk;
                As[kk][mm] = (gm < w.M && gk < w.K) ? w.A[(size_t)gm*w.lda + gk] : 0.f;
            }
        } else {
            int mm = tid & 63, kq = tid >> 6;
            #pragma unroll
            for (int i = 0; i < 4; i++) {
                int kk = kq + i*4;
                int gm = bm + mm, gk = k0 + kk;
                As[kk][mm] = (gm < w.M && gk < w.K) ? w.A[(size_t)gk*w.lda + gm] : 0.f;
            }
        }
        if (!w.trb) {
            int nn = tid & 63, kq = tid >> 6;
            #pragma unroll
            for (int i = 0; i < 4; i++) {
                int kk = kq + i*4;
                int gk = k0 + kk, gn = bn + nn;
                Bs[kk][nn] = (gk < w.K && gn < w.N) ? w.B[(size_t)gk*w.ldb + gn] : 0.f;
            }
        } else {
            int kk = tid & 15, n0 = tid >> 4;
            #pragma unroll
            for (int i = 0; i < 4; i++) {
                int nn = n0 + i*16;
                int gk = k0 + kk, gn = bn + nn;
                Bs[kk][nn] = (gk < w.K && gn < w.N) ? w.B[(size_t)gn*w.ldb + gk] : 0.f;
            }
        }
        __syncthreads();
        #pragma unroll
        for (int kk = 0; kk < 16; kk++) {
            float4 a = *(const float4*)&As[kk][ty*4];
            float4 b = *(const float4*)&Bs[kk][tx*4];
            acc[0][0] += a.x*b.x; acc[0][1] += a.x*b.y; acc[0][2] += a.x*b.z; acc[0][3] += a.x*b.w;
            acc[1][0] += a.y*b.x; acc[1][1] += a.y*b.y; acc[1][2] += a.y*b.z; acc[1][3] += a.y*b.w;
            acc[2][0] += a.z*b.x; acc[2][1] += a.z*b.y; acc[2][2] += a.z*b.z; acc[2][3] += a.z*b.w;
            acc[3][0] += a.w*b.x; acc[3][1] += a.w*b.y; acc[3][2] += a.w*b.z; acc[3][3] += a.w*b.w;
        }
        __syncthreads();
    }
    #pragma unroll
    for (int i = 0; i < 4; i++) {
        int gm = bm + ty*4 + i;
        if (gm >= w.M) continue;
        #pragma unroll
        for (int j = 0; j < 4; j++) {
            int gn = bn + tx*4 + j;
            if (gn >= w.N) continue;
            w.C[(size_t)gm*w.ldc + gn] = acc[i][j];
        }
    }
}

// ---------------- small vector prep ----------------
__global__ void prep_vectors(const float* __restrict__ in_qkv_b, const float* __restrict__ out_qkv_b,
                             const float* __restrict__ in_o_b, const float* __restrict__ out_o_b,
                             const float* __restrict__ fin_qkv_w, const float* __restrict__ fin_qkv_b)
{
    int b = blockIdx.x, t = threadIdx.x; // 320 threads
    if (b < 6) {
        int i = b*320 + t;
        g_biasAll[i] = (i < 960) ? in_qkv_b[i] : out_qkv_b[i - 960];
    } else if (b == 6) {
        float s = fin_qkv_b[t];
        const float* w = fin_qkv_w;
        for (int k = 0; k < 320; k++) s += in_o_b[k] * w[t*320 + k];
        g_cq[t] = s;
    } else if (b == 7) {
        float s = fin_qkv_b[320 + t];
        const float* w = fin_qkv_w + E2;
        for (int k = 0; k < 320; k++) s += in_o_b[k] * w[t*320 + k];
        g_ckin[t] = s;
    } else if (b == 8) {
        float s = fin_qkv_b[320 + t];
        const float* w = fin_qkv_w + E2;
        for (int k = 0; k < 320; k++) s += out_o_b[k] * w[t*320 + k];
        g_ckout[t] = s;
    } else if (b == 9) {
        float s = fin_qkv_b[640 + t];
        const float* w = fin_qkv_w + 2*E2;
        for (int k = 0; k < 320; k++) s += out_o_b[k] * w[t*320 + k];
        g_cvout[t] = s;
    } else if (b == 10) {
        float s = 0.f;
        const float* w = fin_qkv_w + 2*E2;
        for (int k = 0; k < 320; k++) s += (in_o_b[k] - out_o_b[k]) * w[t*320 + k];
        g_Gbig[640*320 + t] = s;
    }
}

// Bpack[k][j] = Gkcat[j][k] (j<640) ; ckin (640) ; ckout (641); pad 0
__global__ void pack_B_kernel()
{
    int k = blockIdx.x;
    int j = threadIdx.x;
    float v;
    if (j < 640)       v = g_Gkcat[(size_t)j*320 + k];
    else if (j == 640) v = g_ckin[k];
    else if (j == 641) v = g_ckout[k];
    else               v = 0.f;
    g_Bpack[(size_t)k*LDP + j] = v;
}

// bias vectors: blocks 0..641 -> bS dot; 642..643 -> bS pad zero; 644..673 -> b2
__global__ void bias_kernel(const float* __restrict__ fin_o_b, const float* __restrict__ Wm)
{
    __shared__ float red[4];
    int b = blockIdx.x, t = threadIdx.x; // 128 threads
    if (b >= 642 && b < 644) { if (t == 0) g_bS[b] = 0.f; return; }
    float p = 0.f;
    if (b < 642) {
        for (int k = t; k < 320; k += 128) p += g_cq[k] * g_Bpack[(size_t)k*LDP + b];
    } else {
        int j = b - 644; // < 30
        for (int k = t; k < 320; k += 128)
            p += g_cvout[k] * g_WoW[k*32 + j] + fin_o_b[k] * Wm[k*OUTD + j];
    }
    #pragma unroll
    for (int o = 16; o; o >>= 1) p += __shfl_down_sync(0xffffffffu, p, o);
    if ((t & 31) == 0) red[t >> 5] = p;
    __syncthreads();
    if (t == 0) {
        float s = red[0] + red[1] + red[2] + red[3];
        if (b < 642) g_bS[b] = s; else g_b2[b - 644] = s;
    }
}

// ---------------- per-node in/out attention (256 threads) ----------------
__global__ __launch_bounds__(256)
void attn_inout_kernel(const float* __restrict__ XQKV,
                       const int* __restrict__ in_idx,
                       const int* __restrict__ out_idx,
                       float* __restrict__ Og)
{
    extern __shared__ float sm[];
    float* Qs = sm;                 // 16*324
    float* Ks = Qs + 16*324;
    float* Vs = Ks + 16*324;
    float* Asc = Vs + 16*324;       // 5*256
    int* tok = (int*)(Asc + 5*256);

    const int node = blockIdx.x;
    const int layer = blockIdx.y;
    const int tid = threadIdx.x;
    const int* idx = layer ? out_idx : in_idx;
    const int qoff = layer * 960;

    if (tid < 16) tok[tid] = (tid == 0) ? node : idx[node*DD + tid - 1];
    __syncthreads();

    for (int t = tid; t < 3*16*80; t += 256) {
        int mat = t / 1280;
        int rem = t - mat*1280;
        int r = rem / 80;
        int e4 = rem - r*80;
        float4 v = *(const float4*)(XQKV + (size_t)tok[r]*1920 + qoff + mat*320 + e4*4);
        *(float4*)(sm + mat*(16*324) + r*324 + e4*4) = v;
    }
    __syncthreads();

    // scores: 80 threads, 4x4 tiles (proven best)
    if (tid < 80) {
        int h = tid / 16;
        int lb = (tid & 15) >> 2;
        int mb = tid & 3;
        float s[4][4] = {};
        const float* qb = Qs + lb*4*324 + h*64;
        const float* kb = Ks + mb*4*324 + h*64;
        #pragma unroll
        for (int k4 = 0; k4 < 16; k4++) {
            float4 qv[4], kv[4];
            #pragma unroll
            for (int i = 0; i < 4; i++) qv[i] = *(const float4*)(qb + i*324 + k4*4);
            #pragma unroll
            for (int j = 0; j < 4; j++) kv[j] = *(const float4*)(kb + j*324 + k4*4);
            #pragma unroll
            for (int i = 0; i < 4; i++)
                #pragma unroll
                for (int j = 0; j < 4; j++)
                    s[i][j] += qv[i].x*kv[j].x + qv[i].y*kv[j].y + qv[i].z*kv[j].z + qv[i].w*kv[j].w;
        }
        #pragma unroll
        for (int i = 0; i < 4; i++)
            #pragma unroll
            for (int j = 0; j < 4; j++)
                Asc[h*256 + (lb*4+i)*16 + (mb*4+j)] = s[i][j] * 0.125f;
    }
    __syncthreads();

    if (tid < 80) {
        int h = tid / 16, l = tid & 15;
        float* row = Asc + h*256 + l*16;
        float mx = row[0];
        #pragma unroll
        for (int m = 1; m < 16; m++) mx = fmaxf(mx, row[m]);
        float e[16]; float ssum = 0.f;
        #pragma unroll
        for (int m = 0; m < 16; m++) { e[m] = __expf(row[m] - mx); ssum += e[m]; }
        float inv = 1.f / ssum;
        #pragma unroll
        for (int m = 0; m < 16; m++) row[m] = e[m] * inv;
    }
    __syncthreads();

    float* Ob = Og + ((size_t)node*32 + layer*16)*320;
    if (tid < 160) {
        int lb = tid / 40, e8 = tid - lb*40;
        int h = e8 >> 3;
        float acc[4][8] = {};
        #pragma unroll
        for (int m = 0; m < 16; m++) {
            const float* vp = Vs + m*324 + e8*8;
            float4 v0 = *(const float4*)vp;
            float4 v1 = *(const float4*)(vp + 4);
            #pragma unroll
            for (int i = 0; i < 4; i++) {
                float a = Asc[h*256 + (lb*4+i)*16 + m];
                acc[i][0] += a*v0.x; acc[i][1] += a*v0.y; acc[i][2] += a*v0.z; acc[i][3] += a*v0.w;
                acc[i][4] += a*v1.x; acc[i][5] += a*v1.y; acc[i][6] += a*v1.z; acc[i][7] += a*v1.w;
            }
        }
        #pragma unroll
        for (int i = 0; i < 4; i++) {
            float* op = Ob + (lb*4+i)*320 + e8*8;
            *(float4*)op       = make_float4(acc[i][0], acc[i][1], acc[i][2], acc[i][3]);
            *(float4*)(op + 4) = make_float4(acc[i][4], acc[i][5], acc[i][6], acc[i][7]);
        }
    }
}

// ---------------- per-node final attention + fused output projection (256 thr) ----------------
__global__ __launch_bounds__(256)
void fin_kernel(const float* __restrict__ Og, const float* __restrict__ S2,
                float* __restrict__ out)
{
    extern __shared__ float sm[];
    float* Os  = sm;             // 32*324
    float* Ss  = Os + 32*324;    // 644
    float* red = Ss + 644;       // 256
    float* aw  = red + 256;      // [0..31]=a, [32]=a_in_tot

    const int node = blockIdx.x;
    const int tid = threadIdx.x;

    for (int t = tid; t < 642; t += 256) Ss[t] = S2[(size_t)node*LDP + t];
    for (int t = tid; t < 32*80; t += 256) {
        int r = t / 80, e4 = t - r*80;
        *(float4*)(Os + r*324 + e4*4) = *(const float4*)(Og + ((size_t)node*32 + r)*320 + e4*4);
    }
    __syncthreads();

    {
        int m = tid >> 3, s8 = tid & 7;
        const float* Sx = Ss + ((m < 16) ? 0 : 320);
        const float* Om = Os + m*324;
        float p = 0.f;
        #pragma unroll
        for (int e = s8*40; e < s8*40 + 40; e++) p += Sx[e] * Om[e];
        red[tid] = p;
    }
    __syncthreads();

    if (tid < 32) {
        float sc = 0.f;
        #pragma unroll
        for (int s = 0; s < 8; s++) sc += red[tid*8 + s];
        sc += (tid < 16) ? Ss[640] : Ss[641];
        sc *= 0.0559016994f;  // 1/sqrt(320)
        float mx = sc;
        #pragma unroll
        for (int o = 16; o; o >>= 1) mx = fmaxf(mx, __shfl_xor_sync(0xffffffffu, mx, o));
        float ex = __expf(sc - mx);
        float ssum = ex;
        #pragma unroll
        for (int o = 16; o; o >>= 1) ssum += __shfl_xor_sync(0xffffffffu, ssum, o);
        float a = ex / ssum;
        aw[tid] = a;
        float ain = (tid < 16) ? a : 0.f;
        #pragma unroll
        for (int o = 16; o; o >>= 1) ain += __shfl_xor_sync(0xffffffffu, ain, o);
        if (tid == 0) aw[32] = ain;
    }
    __syncthreads();

    for (int t = tid; t < 640; t += 256) {
        int which = t / 320, e = t - which*320;
        float acc = 0.f;
        #pragma unroll
        for (int m = 0; m < 16; m++) acc += aw[which*16 + m] * Os[(which*16 + m)*324 + e];
        Ss[t] = acc;
    }
    if (tid == 0) Ss[640] = aw[32];
    __syncthreads();

    if (tid < 240) {
        int j = tid >> 3, s = tid & 7;
        float p = 0.f;
        for (int k = s; k < 641; k += 8) p += Ss[k] * g_GbW[k*32 + j];
        red[tid] = p;
    }
    __syncthreads();
    if (tid < 30) {
        float v = g_b2[tid];
        #pragma unroll
        for (int s = 0; s < 8; s++) v += red[tid*8 + s];
        v = (v > 0.f) ? v : (__expf(v) - 1.f);
        out[(size_t)node*OUTD + tid] = v;
    }
}

// ---------------- host launcher ----------------
extern "C" void kernel_launch(void* const* d_in, const int* in_sizes, int n_in,
                              void* d_out, int out_size)
{
    const float* X        = (const float*)d_in[0];
    const int*   in_idx   = (const int*)  d_in[1];
    const int*   out_idx  = (const int*)  d_in[2];
    const float* in_Wq    = (const float*)d_in[3];
    const float* in_Wk    = (const float*)d_in[4];
    const float* in_Wv    = (const float*)d_in[5];
    const float* in_qkv_w = (const float*)d_in[6];
    const float* in_qkv_b = (const float*)d_in[7];
    const float* in_o_w   = (const float*)d_in[8];
    const float* in_o_b   = (const float*)d_in[9];
    const float* out_Wq   = (const float*)d_in[10];
    const float* out_Wk   = (const float*)d_in[11];
    const float* out_Wv   = (const float*)d_in[12];
    const float* out_qkv_w= (const float*)d_in[13];
    const float* out_qkv_b= (const float*)d_in[14];
    const float* out_o_w  = (const float*)d_in[15];
    const float* out_o_b  = (const float*)d_in[16];
    const float* fin_qkv_w= (const float*)d_in[17];
    const float* fin_qkv_b= (const float*)d_in[18];
    const float* fin_o_w  = (const float*)d_in[19];
    const float* fin_o_b  = (const float*)d_in[20];
    const float* Wm       = (const float*)d_in[21];
    float* out = (float*)d_out;

    float *Fall, *biasAll, *Gq, *Gkcat, *Gbig, *WoW;
    float *Bpack, *Scoef, *GbW, *bS;
    float *XQKV, *Og, *S2;
    cudaGetSymbolAddress((void**)&Fall,   g_Fall);
    cudaGetSymbolAddress((void**)&biasAll,g_biasAll);
    cudaGetSymbolAddress((void**)&Gq,     g_Gq);
    cudaGetSymbolAddress((void**)&Gkcat,  g_Gkcat);
    cudaGetSymbolAddress((void**)&Gbig,   g_Gbig);
    cudaGetSymbolAddress((void**)&WoW,    g_WoW);
    cudaGetSymbolAddress((void**)&Bpack,  g_Bpack);
    cudaGetSymbolAddress((void**)&Scoef,  g_Scoef);
    cudaGetSymbolAddress((void**)&GbW,    g_GbW);
    cudaGetSymbolAddress((void**)&bS,     g_bS);
    cudaGetSymbolAddress((void**)&XQKV,   g_XQKV);
    cudaGetSymbolAddress((void**)&Og,     g_Og);
    cudaGetSymbolAddress((void**)&S2,     g_S2);

    const int attn_smem = (3*16*324 + 5*256)*4 + 16*4;
    const int fin_smem  = (32*324 + 644 + 256 + 40)*4;
    cudaFuncSetAttribute(attn_inout_kernel, cudaFuncAttributeMaxDynamicSharedMemorySize, attn_smem);
    cudaFuncSetAttribute(fin_kernel,        cudaFuncAttributeMaxDynamicSharedMemorySize, fin_smem);

    // 1) small vector prep
    prep_vectors<<<11, 320>>>(in_qkv_b, out_qkv_b, in_o_b, out_o_b, fin_qkv_w, fin_qkv_b);

    // 2) batched weight-prep GEMMs
    WDescArr wd;
    const float* Wc[6]  = {in_Wq, in_Wk, in_Wv, out_Wq, out_Wk, out_Wv};
    const float* Wp[6]  = {in_qkv_w, in_qkv_w + E2, in_qkv_w + 2*E2,
                           out_qkv_w, out_qkv_w + E2, out_qkv_w + 2*E2};
    for (int i = 0; i < 6; i++)
        wd.d[i] = WDesc{Wc[i], Wp[i], Fall + i*320, 320, 320, 1920, 320, 320, 320, 0, 1};
    wd.d[6]  = WDesc{in_o_w,  fin_qkv_w,        Gq,        320, 320, 320, 320, 320, 320, 1, 1};
    wd.d[7]  = WDesc{in_o_w,  fin_qkv_w + E2,   Gkcat,     320, 320, 320, 320, 320, 320, 1, 1};
    wd.d[8]  = WDesc{out_o_w, fin_qkv_w + E2,   Gkcat+E2,  320, 320, 320, 320, 320, 320, 1, 1};
    wd.d[9]  = WDesc{in_o_w,  fin_qkv_w + 2*E2, Gbig,      320, 320, 320, 320, 320, 320, 1, 1};
    wd.d[10] = WDesc{out_o_w, fin_qkv_w + 2*E2, Gbig+E2,   320, 320, 320, 320, 320, 320, 1, 1};
    wd.d[11] = WDesc{fin_o_w, Wm, WoW, 320, OUTD, 32, 320, OUTD, 320, 1, 0};
    wd.d[12] = wd.d[11]; // unused
    gemm_w_batched<<<dim3(5, 5, 12), 256>>>(wd);

    // 3) pack B (ld 644)
    pack_B_kernel<<<320, LDP>>>();

    // 4) Scoef = Gq @ Bpack   [320,642] — tensor cores (pipelined)
    gemm_tc<<<dim3(11, 3), 256>>>(Gq, 320, Bpack, LDP, nullptr, Scoef, LDP, 320, 642, 320);
    // 5) GbW = Gbig @ WoW     [641,30]
    {
        WDescArr w2;
        for (int i = 0; i < 13; i++)
            w2.d[i] = WDesc{Gbig, WoW, GbW, 320, 32, 32, 641, OUTD, 320, 0, 0};
        gemm_w_batched<<<dim3(1, 11, 1), 256>>>(w2);
    }
    // 6) bias vectors (includes bS pad zeroing)
    bias_kernel<<<674, 128>>>(fin_o_b, Wm);

    // 7) XQKV = X @ Fall + biasAll   [10000,1920]  — tensor cores
    gemm_tc<<<dim3(30, 79), 256>>>(X, 320, Fall, 1920, biasAll, XQKV, 1920, NN, 1920, 320);

    // 8) per-node in/out attention -> Og [N,32,320]
    attn_inout_kernel<<<dim3(NN, 2), 256, attn_smem>>>(XQKV, in_idx, out_idx, Og);

    // 9) S2 = O0_in @ Scoef + bS   [10000,642] — tensor cores
    gemm_tc<<<dim3(11, 79), 256>>>(Og, 32*320, Scoef, LDP, bS, S2, LDP, NN, 642, 320);

    // 10) per-node final softmax + weighted sums + fused out projection
    fin_kernel<<<NN, 256, fin_smem>>>(Og, S2, out);
}